// round 14
// baseline (speedup 1.0000x reference)
#include <cuda_runtime.h>
#include <cuda_fp16.h>
#include <math.h>
#include <stdint.h>

#define B_    4
#define L_    16
#define D_    512
#define H_    8
#define HD_   64
#define NTOK_ 1024
#define E3_   1536

// Scratch (allocation-free rule: __device__ globals)
__device__ __half g_Qhf[B_ * H_ * NTOK_ * HD_];
__device__ __half g_Khf[B_ * H_ * NTOK_ * HD_];
__device__ __half g_Vhf[B_ * H_ * NTOK_ * HD_];
__device__ __half g_Xhf[4096 * 512];
__device__ __half g_Whf[1536 * 512];

__device__ __forceinline__ uint32_t smem_u32(const void* p) {
    uint32_t a;
    asm("{ .reg .u64 t; cvta.to.shared.u64 t, %1; cvt.u32.u64 %0, t; }" : "=r"(a) : "l"(p));
    return a;
}
__device__ __forceinline__ void ldsm4(uint32_t* r, uint32_t addr) {
    asm volatile("ldmatrix.sync.aligned.m8n8.x4.shared.b16 {%0,%1,%2,%3}, [%4];"
        : "=r"(r[0]), "=r"(r[1]), "=r"(r[2]), "=r"(r[3]) : "r"(addr));
}
__device__ __forceinline__ void ldsm4t(uint32_t* r, uint32_t addr) {
    asm volatile("ldmatrix.sync.aligned.m8n8.x4.trans.shared.b16 {%0,%1,%2,%3}, [%4];"
        : "=r"(r[0]), "=r"(r[1]), "=r"(r[2]), "=r"(r[3]) : "r"(addr));
}
__device__ __forceinline__ void mma16816h(float* c, const uint32_t* a, uint32_t b0, uint32_t b1) {
    asm volatile("mma.sync.aligned.m16n8k16.row.col.f32.f16.f16.f32 "
        "{%0,%1,%2,%3}, {%4,%5,%6,%7}, {%8,%9}, {%0,%1,%2,%3};"
        : "+f"(c[0]), "+f"(c[1]), "+f"(c[2]), "+f"(c[3])
        : "r"(a[0]), "r"(a[1]), "r"(a[2]), "r"(a[3]), "r"(b0), "r"(b1));
}
__device__ __forceinline__ uint32_t packh2(float a, float b) {
    __half2 t = __floats2half2_rn(a, b);
    return *reinterpret_cast<uint32_t*>(&t);
}

extern __shared__ char smem_raw[];

// ---------------------------------------------------------------------------
// Kernel 0: convert X and W to fp16 (single plane).
// ---------------------------------------------------------------------------
#define XQUADS 524288   // 4096*512/4
#define WQUADS 196608   // 1536*512/4

__global__ __launch_bounds__(256) void split_kernel(const float* __restrict__ x,
                                                    const float* __restrict__ W) {
    int i = blockIdx.x * 256 + threadIdx.x;
    const float4* src;
    __half2* hp;
    int idx;
    if (i < XQUADS) { src = (const float4*)x; hp = (__half2*)g_Xhf; idx = i; }
    else            { src = (const float4*)W; hp = (__half2*)g_Whf; idx = i - XQUADS; }
    float4 v = src[idx];
    hp[idx * 2 + 0] = __floats2half2_rn(v.x, v.y);
    hp[idx * 2 + 1] = __floats2half2_rn(v.z, v.w);
}

// ---------------------------------------------------------------------------
// Kernel 1: QKV GEMM via fp16 mma.sync, K = 512 single plane.
// Epilogue: Q (pre-scaled), K, V all stored as fp16.
// ---------------------------------------------------------------------------
#define GEMM_SMEM (12 * 8192 + 512)

__global__ __launch_bounds__(256, 2) void qkv_gemm(const float* __restrict__ te,
                                                   const float* __restrict__ Wt) {
    uint32_t aBase = smem_u32(smem_raw);
    uint32_t bBase = aBase + 6 * 8192;
    float* s_tq = (float*)(smem_raw + 12 * 8192);

    int tid = threadIdx.x;
    int m0 = blockIdx.y * 128, e0 = blockIdx.x * 128;
    int bb = m0 >> 10, l0 = (m0 >> 6) & 15, third = e0 >> 9;

    int mld = tid >> 1;
    int kc0 = (tid & 1) * 2;
    int swm = (mld >> 1) & 3;
    uint32_t dA0 = aBase + mld * 64, dB0 = bBase + mld * 64;
    const __half* Asrc = g_Xhf + (size_t)(m0 + mld) * 512;
    const __half* Bsrc = g_Whf + (size_t)(e0 + mld) * 512;

#define ISSUE(ki, st) do {                                                      \
    int _kb = (ki) * 32;                                                        \
    _Pragma("unroll")                                                           \
    for (int _j = 0; _j < 2; _j++) {                                            \
        int _kc = kc0 + _j;                                                     \
        const void* _sa = Asrc + _kb + _kc * 8;                                 \
        const void* _sb = Bsrc + _kb + _kc * 8;                                 \
        uint32_t _da = dA0 + (st) * 8192 + (((_kc) ^ swm) << 4);                \
        uint32_t _db = dB0 + (st) * 8192 + (((_kc) ^ swm) << 4);                \
        asm volatile("cp.async.cg.shared.global [%0], [%1], 16;" :: "r"(_da), "l"(_sa)); \
        asm volatile("cp.async.cg.shared.global [%0], [%1], 16;" :: "r"(_db), "l"(_sb)); \
    }                                                                           \
    asm volatile("cp.async.commit_group;");                                     \
} while (0)

    ISSUE(0, 0);
    ISSUE(1, 1);
    ISSUE(2, 2);
    ISSUE(3, 3);

    // in-block tqkv overlaps with prefetch latency (fp32)
    {
        int outi = tid >> 1, half = tid & 1;
        int fr = outi >> 6, hd = outi & 63;
        const float4* tp = (const float4*)(te + (size_t)(bb * 16 + l0 + fr) * D_) + half * 64;
        const float4* wp = (const float4*)(Wt + (size_t)(third * 64 + hd) * D_) + half * 64;
        float acc = 0.f;
#pragma unroll 8
        for (int k = 0; k < 64; k++) {
            float4 a = tp[k], w = wp[k];
            acc += a.x * w.x + a.y * w.y + a.z * w.z + a.w * w.w;
        }
        acc += __shfl_xor_sync(0xffffffffu, acc, 1);
        if (!half) s_tq[outi] = acc;
    }

    int lane = tid & 31, warp = tid >> 5;
    int wm = warp & 1, wn = warp >> 1;
    uint32_t aAddr[4]; int aXor[4];
    int rA = lane & 15, kcbA = lane >> 4;
#pragma unroll
    for (int im = 0; im < 4; im++) {
        int mr = wm * 64 + im * 16 + rA;
        aAddr[im] = aBase + mr * 64;
        aXor[im] = (mr >> 1) & 3;
    }
    uint32_t bAddr[2]; int bXor[2];
    int kcbB = (lane >> 3) & 1;
#pragma unroll
    for (int p = 0; p < 2; p++) {
        int nr = wn * 32 + p * 16 + (lane & 7) + ((lane >> 4) << 3);
        bAddr[p] = bBase + nr * 64;
        bXor[p] = (nr >> 1) & 3;
    }

    float c[4][4][4] = {};

    for (int it = 0; it < 8; it++) {
        if (it < 7) {
            asm volatile("cp.async.wait_group 2;" ::: "memory");
        } else {
            asm volatile("cp.async.wait_group 0;" ::: "memory");
        }
        __syncthreads();
        int k0 = 2 * it;
        if (k0 + 4 < 16) ISSUE(k0 + 4, (k0 + 4) % 6);
        if (k0 + 5 < 16) ISSUE(k0 + 5, (k0 + 5) % 6);
#pragma unroll
        for (int half = 0; half < 2; half++) {
            int cur = (k0 + half) % 6;
#pragma unroll
            for (int s = 0; s < 2; s++) {
                uint32_t a[4][4];
#pragma unroll
                for (int im = 0; im < 4; im++)
                    ldsm4(a[im], aAddr[im] + cur * 8192 + (((kcbA + 2 * s) ^ aXor[im]) << 4));
                uint32_t bq[2][4];
#pragma unroll
                for (int p = 0; p < 2; p++)
                    ldsm4(bq[p], bAddr[p] + cur * 8192 + (((kcbB + 2 * s) ^ bXor[p]) << 4));
#pragma unroll
                for (int im = 0; im < 4; im++)
#pragma unroll
                    for (int in = 0; in < 4; in++)
                        mma16816h(c[im][in], a[im], bq[in >> 1][(in & 1) * 2], bq[in >> 1][(in & 1) * 2 + 1]);
            }
        }
    }

    // ---- unified fp16 coalesced epilogue ----
    __syncthreads();
    const float inv_scale = 0.044194173824159216f;  // 1/sqrt(512)
    float oscale = (third == 0) ? inv_scale : 1.0f;
    int gid = lane >> 2, tig = lane & 3;

    uint8_t* stH = (uint8_t*)smem_raw;   // [128][272B] fp16 plane
#pragma unroll
    for (int im = 0; im < 4; im++) {
#pragma unroll
        for (int hrow = 0; hrow < 2; hrow++) {
            int row = wm * 64 + im * 16 + gid + hrow * 8;
            int frl = ((m0 + row) >> 6) & 1;
#pragma unroll
            for (int in = 0; in < 4; in++) {
                int col = wn * 32 + in * 8 + 2 * tig;
                int hd = col & 63;
                float v0 = (c[im][in][2 * hrow + 0] + s_tq[frl * 64 + hd]) * oscale;
                float v1 = (c[im][in][2 * hrow + 1] + s_tq[frl * 64 + hd + 1]) * oscale;
                *(uint32_t*)(stH + row * 272 + col * 2) = packh2(v0, v1);
            }
        }
    }
    __syncthreads();
    __half* dst = (third == 0) ? g_Qhf : ((third == 1) ? g_Khf : g_Vhf);
    for (int cc = tid; cc < 2048; cc += 256) {
        int row = cc >> 4, ch = cc & 15;
        int col = ch * 8;
        int e = e0 + col;
        int h = (e >> 6) & 7, hd = col & 63;
        int grow = m0 + row;
        int b = grow >> 10, l = (grow >> 6) & 15, nt = grow & 63;
        size_t off = (size_t)((b * H_ + h) * NTOK_ + l * 64 + nt) * HD_ + hd;
        *(uint4*)(dst + off) = *(const uint4*)(stH + row * 272 + ch * 16);
    }
}

// ---------------------------------------------------------------------------
// Kernel 2: fused attention, 2 q-frames per block (128 q-rows), 256 threads.
// 8 warps = 2 groups of 4 (group 0: frame ql0 rows 0-63; group 1: ql1 rows 64-127).
// Union frame list with per-group validity flags; private softmax state.
// smem (bytes):
//   [0, 32768)      KV[2 stages][K 8192 | V 8192]
//       alias (prologue): Et0/Et1 fp32 @16384 (8704B, inside stage 1)
//   [32768, 49152)  Qhf fp16 128x64 swizzled (16KB)
//   [49152, 57856)  bias fp32 [128][17]
//   [57856, 57924)  list (16 entries + count)
//   final O staging: fp32 [128][68] @0 (34816B, overlays KV+Qhf, both dead)
// ---------------------------------------------------------------------------
#define ATT_KV     0
#define ATT_ET0    16384
#define ATT_ET1    (ATT_ET0 + 16 * 68 * 4)
#define ATT_QHF    32768
#define ATT_BIAS   49152
#define ATT_LIST   (ATT_BIAS + 128 * 17 * 4)
#define ATT_SMEM   (ATT_LIST + 68)

__global__ __launch_bounds__(256, 2) void attn_kernel(const int* __restrict__ pos,
                                                      const int* __restrict__ mask,
                                                      const float* __restrict__ emb,
                                                      float* __restrict__ out) {
    uint32_t sbase = smem_u32(smem_raw);
    float* Et0 = (float*)(smem_raw + ATT_ET0);   // [16][68]
    float* Et1 = (float*)(smem_raw + ATT_ET1);
    float (*bias)[17] = (float(*)[17])(smem_raw + ATT_BIAS);
    int* list = (int*)(smem_raw + ATT_LIST);

    int qp = 7 - blockIdx.x;                     // heavy-first
    int ql0 = 2 * qp, ql1 = 2 * qp + 1;
    int h = blockIdx.y, b = blockIdx.z;
    int tid = threadIdx.x;
    int lane = tid & 31, w = tid >> 5;
    int r0 = w * 16;                             // global q-row base 0..112
    int group = w >> 2;                          // 0: ql0, 1: ql1
    int bh = b * H_ + h;

    const __half* Qsrc = g_Qhf + ((size_t)bh * NTOK_ + ql0 * 64) * HD_;  // 128 rows
    const __half* Ksrc = g_Khf + (size_t)bh * NTOK_ * HD_;
    const __half* Vsrc = g_Vhf + (size_t)bh * NTOK_ * HD_;

    // ---- union frame list with validity flags (tid 0)
    if (tid == 0) {
        int nu = 0;
        const int* mr0 = mask + (b * L_ + ql0) * L_;
        const int* mr1 = mask + (b * L_ + ql1) * L_;
#pragma unroll
        for (int kl = 0; kl < L_; kl++) {
            int fA = (mr0[kl] != 0), fB = (mr1[kl] != 0);
            if (fA | fB) list[nu++] = kl | (fA << 8) | (fB << 9);
        }
        list[16] = nu;
    }

    // ---- Et loads (both frames)
    for (int i = tid; i < 1024; i += 256) {
        int kl = i >> 6, c = i & 63;
        int p0 = pos[(b * L_ + ql0) * L_ + kl];
        p0 = min(max(p0, -8), 8) + 8;
        Et0[kl * 68 + c] = emb[p0 * HD_ + c];
        int p1 = pos[(b * L_ + ql1) * L_ + kl];
        p1 = min(max(p1, -8), 8) + 8;
        Et1[kl * 68 + c] = emb[p1 * HD_ + c];
    }

    // ---- issue Q tile cp.async (128 rows x 64 fp16 = 16KB, swizzled)
#pragma unroll
    for (int c = 0; c < 4; c++) {
        int lin = c * 256 + tid;
        int row = lin >> 3, ch = lin & 7;
        uint32_t da = sbase + ATT_QHF + row * 128 + ((ch ^ (row & 7)) << 4);
        asm volatile("cp.async.cg.shared.global [%0], [%1], 16;"
                     :: "r"(da), "l"(Qsrc + row * 64 + ch * 8));
    }
    asm volatile("cp.async.commit_group;");

    __syncthreads();   // list + Et visible
    int nu = list[16];

#define ISSUE_FRAME(f, stage) do {                                              \
    _Pragma("unroll")                                                           \
    for (int _c = 0; _c < 4; _c++) {                                            \
        int _lin = _c * 256 + tid;                                              \
        int _tile = _lin >> 9, _wi = _lin & 511;                                \
        int _row = _wi >> 3, _ch = _wi & 7;                                     \
        const __half* _s = (_tile ? Vsrc : Ksrc) + (f) * 4096 + _row * 64 + _ch * 8; \
        uint32_t _da = sbase + ATT_KV + (stage) * 16384 + _tile * 8192          \
                       + _row * 128 + ((_ch ^ (_row & 7)) << 4);                \
        asm volatile("cp.async.cg.shared.global [%0], [%1], 16;"                \
                     :: "r"(_da), "l"(_s));                                     \
    }                                                                           \
    asm volatile("cp.async.commit_group;");                                     \
} while (0)

    ISSUE_FRAME(list[0] & 15, 0);
    asm volatile("cp.async.wait_group 1;" ::: "memory");   // Q arrived
    __syncthreads();                                        // all threads' Q in smem

    // ---- bias[r][kl] from fp16 Q (deswizzled) . Et
#pragma unroll
    for (int u = 0; u < 8; u++) {
        int id = tid + u * 256;
        int r = id >> 4, kl = id & 15;
        const float* erow = ((r < 64) ? Et0 : Et1) + kl * 68;
        float acc = 0.f;
#pragma unroll
        for (int ch = 0; ch < 8; ch++) {
            uint4 qv = *(const uint4*)(smem_raw + ATT_QHF + r * 128 + ((ch ^ (r & 7)) << 4));
            const __half2* hh = (const __half2*)&qv;
#pragma unroll
            for (int t = 0; t < 4; t++) {
                float2 f = __half22float2(hh[t]);
                acc += f.x * erow[ch * 8 + 2 * t] + f.y * erow[ch * 8 + 2 * t + 1];
            }
        }
        bias[r][kl] = acc;
    }

    // ---- Q A-fragments
    uint32_t qh[4][4];
    {
        int lrow = (lane & 7) + 8 * ((lane >> 3) & 1);
        int khalf = lane >> 4;
#pragma unroll
        for (int kt = 0; kt < 4; kt++) {
            int qr = r0 + lrow;
            int qc = kt * 2 + khalf;
            uint32_t off = qr * 128 + ((qc ^ (qr & 7)) << 4);
            ldsm4(qh[kt], sbase + ATT_QHF + off);
        }
    }
    __syncthreads();   // bias written; Et region (KV stage 1) may be overwritten

    int g4 = lane >> 2;
    float m0r = -INFINITY, m1r = -INFINITY, l0r = 0.f, l1r = 0.f;
    float O[8][4] = {};

    int klrow = (lane & 7) + 8 * (lane >> 4);
    int kchalf = (lane >> 3) & 1;
    int vlrow = (lane & 7) + 8 * ((lane >> 3) & 1);
    int vchalf = lane >> 4;

    for (int j = 0; j < nu; j++) {
        int stage = j & 1;
        if (j + 1 < nu) {
            ISSUE_FRAME(list[j + 1] & 15, (j + 1) & 1);
            asm volatile("cp.async.wait_group 1;" ::: "memory");
        } else {
            asm volatile("cp.async.wait_group 0;" ::: "memory");
        }
        __syncthreads();
        int ent = list[j];
        int kl = ent & 15;
        int myf = (ent >> (8 + group)) & 1;

        if (myf) {
            uint32_t khB = sbase + ATT_KV + stage * 16384;
            uint32_t vhB = khB + 8192;

            // ---- S = bias + Qhf.Khf
            float S[8][4];
            float bb0 = bias[r0 + g4][kl], bb1 = bias[r0 + 8 + g4][kl];
#pragma unroll
            for (int nt = 0; nt < 8; nt++) {
                S[nt][0] = bb0; S[nt][1] = bb0; S[nt][2] = bb1; S[nt][3] = bb1;
            }
#pragma unroll
            for (int kt = 0; kt < 4; kt++) {
#pragma unroll
                for (int np = 0; np < 4; np++) {
                    int nr = np * 16 + klrow;
                    int kc = kt * 2 + kchalf;
                    uint32_t off = nr * 128 + ((kc ^ (nr & 7)) << 4);
                    uint32_t kh[4];
                    ldsm4(kh, khB + off);
                    mma16816h(S[2 * np],     qh[kt], kh[0], kh[1]);
                    mma16816h(S[2 * np + 1], qh[kt], kh[2], kh[3]);
                }
            }

            // ---- online softmax
            float mx0 = -INFINITY, mx1 = -INFINITY;
#pragma unroll
            for (int nt = 0; nt < 8; nt++) {
                mx0 = fmaxf(mx0, fmaxf(S[nt][0], S[nt][1]));
                mx1 = fmaxf(mx1, fmaxf(S[nt][2], S[nt][3]));
            }
            mx0 = fmaxf(mx0, __shfl_xor_sync(0xffffffffu, mx0, 1));
            mx0 = fmaxf(mx0, __shfl_xor_sync(0xffffffffu, mx0, 2));
            mx1 = fmaxf(mx1, __shfl_xor_sync(0xffffffffu, mx1, 1));
            mx1 = fmaxf(mx1, __shfl_xor_sync(0xffffffffu, mx1, 2));
            float mn0 = fmaxf(m0r, mx0), mn1 = fmaxf(m1r, mx1);
            float corr0 = __expf(m0r - mn0), corr1 = __expf(m1r - mn1);
            float sum0 = 0.f, sum1 = 0.f;
#pragma unroll
            for (int nt = 0; nt < 8; nt++) {
                S[nt][0] = __expf(S[nt][0] - mn0); S[nt][1] = __expf(S[nt][1] - mn0);
                S[nt][2] = __expf(S[nt][2] - mn1); S[nt][3] = __expf(S[nt][3] - mn1);
                sum0 += S[nt][0] + S[nt][1];
                sum1 += S[nt][2] + S[nt][3];
            }
            sum0 += __shfl_xor_sync(0xffffffffu, sum0, 1);
            sum0 += __shfl_xor_sync(0xffffffffu, sum0, 2);
            sum1 += __shfl_xor_sync(0xffffffffu, sum1, 1);
            sum1 += __shfl_xor_sync(0xffffffffu, sum1, 2);
            l0r = l0r * corr0 + sum0; m0r = mn0;
            l1r = l1r * corr1 + sum1; m1r = mn1;

            // ---- P fp16 A-fragments
            uint32_t ph[4][4];
#pragma unroll
            for (int kt = 0; kt < 4; kt++) {
#pragma unroll
                for (int q = 0; q < 4; q++) {
                    int nt = 2 * kt + (q >> 1);
                    ph[kt][q] = packh2(S[nt][(q & 1) * 2], S[nt][(q & 1) * 2 + 1]);
                }
            }

            // ---- O = O*corr + Phf.Vhf
#pragma unroll
            for (int nt = 0; nt < 8; nt++) {
                O[nt][0] *= corr0; O[nt][1] *= corr0; O[nt][2] *= corr1; O[nt][3] *= corr1;
            }
#pragma unroll
            for (int kt = 0; kt < 4; kt++) {
#pragma unroll
                for (int np = 0; np < 4; np++) {
                    int vr = kt * 16 + vlrow;
                    int vc = np * 2 + vchalf;
                    uint32_t off = vr * 128 + ((vc ^ (vr & 7)) << 4);
                    uint32_t vh[4];
                    ldsm4t(vh, vhB + off);
                    mma16816h(O[2 * np],     ph[kt], vh[0], vh[1]);
                    mma16816h(O[2 * np + 1], ph[kt], vh[2], vh[3]);
                }
            }
        }
        __syncthreads();
    }

    // ---- stage normalized O (128 rows), coalesced store
    {
        float inv0 = 1.f / l0r, inv1 = 1.f / l1r;
        float* stage = (float*)smem_raw;   // [128][68] fp32 over dead KV+Qhf
        int cl = 2 * (lane & 3);
#pragma unroll
        for (int nt = 0; nt < 8; nt++) {
            stage[(r0 + g4) * 68 + nt * 8 + cl]         = O[nt][0] * inv0;
            stage[(r0 + g4) * 68 + nt * 8 + cl + 1]     = O[nt][1] * inv0;
            stage[(r0 + 8 + g4) * 68 + nt * 8 + cl]     = O[nt][2] * inv1;
            stage[(r0 + 8 + g4) * 68 + nt * 8 + cl + 1] = O[nt][3] * inv1;
        }
        __syncthreads();
        float* ob = out + (size_t)((b * L_ + ql0) * 64) * D_ + h * HD_;
        for (int cc = tid; cc < 2048; cc += 256) {
            int row = cc >> 4, ch = cc & 15;
            float4 v = *(const float4*)(stage + row * 68 + ch * 4);
            *(float4*)(ob + (size_t)row * D_ + ch * 4) = v;
        }
    }
}

// ---------------------------------------------------------------------------
extern "C" void kernel_launch(void* const* d_in, const int* in_sizes, int n_in,
                              void* d_out, int out_size) {
    const float* x    = (const float*)d_in[0];
    const float* te   = (const float*)d_in[1];
    const int*   pos  = (const int*)d_in[2];
    const int*   mask = (const int*)d_in[3];
    const float* Wqkv = (const float*)d_in[4];
    const float* Wt   = (const float*)d_in[5];
    const float* emb  = (const float*)d_in[6];
    float* out = (float*)d_out;

    cudaFuncSetAttribute(qkv_gemm, cudaFuncAttributeMaxDynamicSharedMemorySize, GEMM_SMEM);
    cudaFuncSetAttribute(attn_kernel, cudaFuncAttributeMaxDynamicSharedMemorySize, ATT_SMEM);

    split_kernel<<<(XQUADS + WQUADS) / 256, 256>>>(x, Wqkv);
    qkv_gemm<<<dim3(E3_ / 128, 4096 / 128), 256, GEMM_SMEM>>>(te, Wt);
    attn_kernel<<<dim3(8, H_, B_), 256, ATT_SMEM>>>(pos, mask, emb, out);
}

// round 15
// speedup vs baseline: 1.0990x; 1.0990x over previous
#include <cuda_runtime.h>
#include <cuda_fp16.h>
#include <math.h>
#include <stdint.h>

#define B_    4
#define L_    16
#define D_    512
#define H_    8
#define HD_   64
#define NTOK_ 1024
#define E3_   1536

// Scratch (allocation-free rule: __device__ globals)
__device__ __half g_Qhf[B_ * H_ * NTOK_ * HD_];
__device__ __half g_Khf[B_ * H_ * NTOK_ * HD_];
__device__ __half g_Vhf[B_ * H_ * NTOK_ * HD_];
__device__ __half g_Xhf[4096 * 512];
__device__ __half g_Whf[1536 * 512];

__device__ __forceinline__ uint32_t smem_u32(const void* p) {
    uint32_t a;
    asm("{ .reg .u64 t; cvta.to.shared.u64 t, %1; cvt.u32.u64 %0, t; }" : "=r"(a) : "l"(p));
    return a;
}
__device__ __forceinline__ void ldsm4(uint32_t* r, uint32_t addr) {
    asm volatile("ldmatrix.sync.aligned.m8n8.x4.shared.b16 {%0,%1,%2,%3}, [%4];"
        : "=r"(r[0]), "=r"(r[1]), "=r"(r[2]), "=r"(r[3]) : "r"(addr));
}
__device__ __forceinline__ void ldsm4t(uint32_t* r, uint32_t addr) {
    asm volatile("ldmatrix.sync.aligned.m8n8.x4.trans.shared.b16 {%0,%1,%2,%3}, [%4];"
        : "=r"(r[0]), "=r"(r[1]), "=r"(r[2]), "=r"(r[3]) : "r"(addr));
}
__device__ __forceinline__ void mma16816h(float* c, const uint32_t* a, uint32_t b0, uint32_t b1) {
    asm volatile("mma.sync.aligned.m16n8k16.row.col.f32.f16.f16.f32 "
        "{%0,%1,%2,%3}, {%4,%5,%6,%7}, {%8,%9}, {%0,%1,%2,%3};"
        : "+f"(c[0]), "+f"(c[1]), "+f"(c[2]), "+f"(c[3])
        : "r"(a[0]), "r"(a[1]), "r"(a[2]), "r"(a[3]), "r"(b0), "r"(b1));
}
__device__ __forceinline__ uint32_t packh2(float a, float b) {
    __half2 t = __floats2half2_rn(a, b);
    return *reinterpret_cast<uint32_t*>(&t);
}

extern __shared__ char smem_raw[];

// ---------------------------------------------------------------------------
// Kernel 0: convert X and W to fp16 (single plane).
// ---------------------------------------------------------------------------
#define XQUADS 524288   // 4096*512/4
#define WQUADS 196608   // 1536*512/4

__global__ __launch_bounds__(256) void split_kernel(const float* __restrict__ x,
                                                    const float* __restrict__ W) {
    int i = blockIdx.x * 256 + threadIdx.x;
    const float4* src;
    __half2* hp;
    int idx;
    if (i < XQUADS) { src = (const float4*)x; hp = (__half2*)g_Xhf; idx = i; }
    else            { src = (const float4*)W; hp = (__half2*)g_Whf; idx = i - XQUADS; }
    float4 v = src[idx];
    hp[idx * 2 + 0] = __floats2half2_rn(v.x, v.y);
    hp[idx * 2 + 1] = __floats2half2_rn(v.z, v.w);
}

// ---------------------------------------------------------------------------
// Kernel 1: QKV GEMM via fp16 mma.sync, K = 512 single plane.
// Epilogue: Q (pre-scaled), K, V all stored as fp16.  (r14, passing)
// ---------------------------------------------------------------------------
#define GEMM_SMEM (12 * 8192 + 512)

__global__ __launch_bounds__(256, 2) void qkv_gemm(const float* __restrict__ te,
                                                   const float* __restrict__ Wt) {
    uint32_t aBase = smem_u32(smem_raw);
    uint32_t bBase = aBase + 6 * 8192;
    float* s_tq = (float*)(smem_raw + 12 * 8192);

    int tid = threadIdx.x;
    int m0 = blockIdx.y * 128, e0 = blockIdx.x * 128;
    int bb = m0 >> 10, l0 = (m0 >> 6) & 15, third = e0 >> 9;

    int mld = tid >> 1;
    int kc0 = (tid & 1) * 2;
    int swm = (mld >> 1) & 3;
    uint32_t dA0 = aBase + mld * 64, dB0 = bBase + mld * 64;
    const __half* Asrc = g_Xhf + (size_t)(m0 + mld) * 512;
    const __half* Bsrc = g_Whf + (size_t)(e0 + mld) * 512;

#define ISSUE(ki, st) do {                                                      \
    int _kb = (ki) * 32;                                                        \
    _Pragma("unroll")                                                           \
    for (int _j = 0; _j < 2; _j++) {                                            \
        int _kc = kc0 + _j;                                                     \
        const void* _sa = Asrc + _kb + _kc * 8;                                 \
        const void* _sb = Bsrc + _kb + _kc * 8;                                 \
        uint32_t _da = dA0 + (st) * 8192 + (((_kc) ^ swm) << 4);                \
        uint32_t _db = dB0 + (st) * 8192 + (((_kc) ^ swm) << 4);                \
        asm volatile("cp.async.cg.shared.global [%0], [%1], 16;" :: "r"(_da), "l"(_sa)); \
        asm volatile("cp.async.cg.shared.global [%0], [%1], 16;" :: "r"(_db), "l"(_sb)); \
    }                                                                           \
    asm volatile("cp.async.commit_group;");                                     \
} while (0)

    ISSUE(0, 0);
    ISSUE(1, 1);
    ISSUE(2, 2);
    ISSUE(3, 3);

    // in-block tqkv overlaps with prefetch latency (fp32)
    {
        int outi = tid >> 1, half = tid & 1;
        int fr = outi >> 6, hd = outi & 63;
        const float4* tp = (const float4*)(te + (size_t)(bb * 16 + l0 + fr) * D_) + half * 64;
        const float4* wp = (const float4*)(Wt + (size_t)(third * 64 + hd) * D_) + half * 64;
        float acc = 0.f;
#pragma unroll 8
        for (int k = 0; k < 64; k++) {
            float4 a = tp[k], w = wp[k];
            acc += a.x * w.x + a.y * w.y + a.z * w.z + a.w * w.w;
        }
        acc += __shfl_xor_sync(0xffffffffu, acc, 1);
        if (!half) s_tq[outi] = acc;
    }

    int lane = tid & 31, warp = tid >> 5;
    int wm = warp & 1, wn = warp >> 1;
    uint32_t aAddr[4]; int aXor[4];
    int rA = lane & 15, kcbA = lane >> 4;
#pragma unroll
    for (int im = 0; im < 4; im++) {
        int mr = wm * 64 + im * 16 + rA;
        aAddr[im] = aBase + mr * 64;
        aXor[im] = (mr >> 1) & 3;
    }
    uint32_t bAddr[2]; int bXor[2];
    int kcbB = (lane >> 3) & 1;
#pragma unroll
    for (int p = 0; p < 2; p++) {
        int nr = wn * 32 + p * 16 + (lane & 7) + ((lane >> 4) << 3);
        bAddr[p] = bBase + nr * 64;
        bXor[p] = (nr >> 1) & 3;
    }

    float c[4][4][4] = {};

    for (int it = 0; it < 8; it++) {
        if (it < 7) {
            asm volatile("cp.async.wait_group 2;" ::: "memory");
        } else {
            asm volatile("cp.async.wait_group 0;" ::: "memory");
        }
        __syncthreads();
        int k0 = 2 * it;
        if (k0 + 4 < 16) ISSUE(k0 + 4, (k0 + 4) % 6);
        if (k0 + 5 < 16) ISSUE(k0 + 5, (k0 + 5) % 6);
#pragma unroll
        for (int half = 0; half < 2; half++) {
            int cur = (k0 + half) % 6;
#pragma unroll
            for (int s = 0; s < 2; s++) {
                uint32_t a[4][4];
#pragma unroll
                for (int im = 0; im < 4; im++)
                    ldsm4(a[im], aAddr[im] + cur * 8192 + (((kcbA + 2 * s) ^ aXor[im]) << 4));
                uint32_t bq[2][4];
#pragma unroll
                for (int p = 0; p < 2; p++)
                    ldsm4(bq[p], bAddr[p] + cur * 8192 + (((kcbB + 2 * s) ^ bXor[p]) << 4));
#pragma unroll
                for (int im = 0; im < 4; im++)
#pragma unroll
                    for (int in = 0; in < 4; in++)
                        mma16816h(c[im][in], a[im], bq[in >> 1][(in & 1) * 2], bq[in >> 1][(in & 1) * 2 + 1]);
            }
        }
    }

    // ---- unified fp16 coalesced epilogue ----
    __syncthreads();
    const float inv_scale = 0.044194173824159216f;  // 1/sqrt(512)
    float oscale = (third == 0) ? inv_scale : 1.0f;
    int gid = lane >> 2, tig = lane & 3;

    uint8_t* stH = (uint8_t*)smem_raw;   // [128][272B] fp16 plane
#pragma unroll
    for (int im = 0; im < 4; im++) {
#pragma unroll
        for (int hrow = 0; hrow < 2; hrow++) {
            int row = wm * 64 + im * 16 + gid + hrow * 8;
            int frl = ((m0 + row) >> 6) & 1;
#pragma unroll
            for (int in = 0; in < 4; in++) {
                int col = wn * 32 + in * 8 + 2 * tig;
                int hd = col & 63;
                float v0 = (c[im][in][2 * hrow + 0] + s_tq[frl * 64 + hd]) * oscale;
                float v1 = (c[im][in][2 * hrow + 1] + s_tq[frl * 64 + hd + 1]) * oscale;
                *(uint32_t*)(stH + row * 272 + col * 2) = packh2(v0, v1);
            }
        }
    }
    __syncthreads();
    __half* dst = (third == 0) ? g_Qhf : ((third == 1) ? g_Khf : g_Vhf);
    for (int cc = tid; cc < 2048; cc += 256) {
        int row = cc >> 4, ch = cc & 15;
        int col = ch * 8;
        int e = e0 + col;
        int h = (e >> 6) & 7, hd = col & 63;
        int grow = m0 + row;
        int b = grow >> 10, l = (grow >> 6) & 15, nt = grow & 63;
        size_t off = (size_t)((b * H_ + h) * NTOK_ + l * 64 + nt) * HD_ + hd;
        *(uint4*)(dst + off) = *(const uint4*)(stH + row * 272 + ch * 16);
    }
}

// ---------------------------------------------------------------------------
// Kernel 2: fused attention — r13 structure (1 q-frame/block, 128 threads,
// 512 blocks, private frame list) + fp16 Q path (cp.async, no convert).
// smem (bytes):
//   [0, 32768)      KV[2 stages][K 8192 | V 8192]
//       alias (prologue): Et fp32 [16][68] @16384 (4352B, inside stage 1)
//   [32768, 40960)  Qhf fp16 64x64 swizzled (8KB)
//   [40960, 45312)  bias fp32 [64][17]
//   [45312, 45380)  list
//   final O staging: fp32 [64][68] @0 (17408B over dead KV)
// ---------------------------------------------------------------------------
#define ATT_KV     0
#define ATT_ET     16384
#define ATT_QHF    32768
#define ATT_BIAS   40960
#define ATT_LIST   (ATT_BIAS + 64 * 17 * 4)
#define ATT_SMEM   (ATT_LIST + 68)

__global__ __launch_bounds__(128, 2) void attn_kernel(const int* __restrict__ pos,
                                                      const int* __restrict__ mask,
                                                      const float* __restrict__ emb,
                                                      float* __restrict__ out) {
    uint32_t sbase = smem_u32(smem_raw);
    float* Et = (float*)(smem_raw + ATT_ET);          // [16][68]
    float (*bias)[17] = (float(*)[17])(smem_raw + ATT_BIAS);
    int* list = (int*)(smem_raw + ATT_LIST);

    int ql = (L_ - 1) - blockIdx.x;                   // heavy-first
    int h = blockIdx.y, b = blockIdx.z;
    int tid = threadIdx.x;
    int lane = tid & 31, w = tid >> 5;
    int r0 = w * 16;
    int bh = b * H_ + h;

    const __half* Qsrc = g_Qhf + ((size_t)bh * NTOK_ + ql * 64) * HD_;
    const __half* Ksrc = g_Khf + (size_t)bh * NTOK_ * HD_;
    const __half* Vsrc = g_Vhf + (size_t)bh * NTOK_ * HD_;

    // ---- valid-frame list
    if (tid == 0) {
        int nvl = 0;
        const int* mrow = mask + (b * L_ + ql) * L_;
#pragma unroll
        for (int kl = 0; kl < L_; kl++)
            if (mrow[kl] != 0) list[nvl++] = kl;
        list[16] = nvl;
    }

    // ---- Et loads (fp32, plain stores into KV-stage-1 alias)
    for (int i = tid; i < 1024; i += 128) {
        int kl = i >> 6, c = i & 63;
        int p = pos[(b * L_ + ql) * L_ + kl];
        p = min(max(p, -8), 8) + 8;
        Et[kl * 68 + c] = emb[p * HD_ + c];
    }

    // ---- Q tile cp.async (64 rows x 128B swizzled = 8KB; 4 chunks/thread)
#pragma unroll
    for (int c = 0; c < 4; c++) {
        int lin = c * 128 + tid;
        int row = lin >> 3, ch = lin & 7;
        uint32_t da = sbase + ATT_QHF + row * 128 + ((ch ^ (row & 7)) << 4);
        asm volatile("cp.async.cg.shared.global [%0], [%1], 16;"
                     :: "r"(da), "l"(Qsrc + row * 64 + ch * 8));
    }
    asm volatile("cp.async.commit_group;");

    __syncthreads();   // list + Et visible
    int nv = list[16];

    // per-frame cp.async: warp pair per tile (w>>1: 0=K, 1=V), 8 chunks each
    const __half* mysrc = (w >> 1) ? Vsrc : Ksrc;
    int halfw = w & 1;
    uint32_t mydst = sbase + ATT_KV + (w >> 1) * 8192;

#define ISSUE_FRAME(f, stage) do {                                              \
    const __half* _s = mysrc + (f) * 4096;                                      \
    uint32_t _d = mydst + (stage) * 16384;                                      \
    _Pragma("unroll")                                                           \
    for (int _c = 0; _c < 8; _c++) {                                            \
        int _lin = halfw * 256 + _c * 32 + lane;                                \
        int _row = _lin >> 3, _ch = _lin & 7;                                   \
        uint32_t _da = _d + _row * 128 + ((_ch ^ (_row & 7)) << 4);             \
        asm volatile("cp.async.cg.shared.global [%0], [%1], 16;"                \
                     :: "r"(_da), "l"(_s + _row * 64 + _ch * 8));               \
    }                                                                           \
    asm volatile("cp.async.commit_group;");                                     \
} while (0)

    ISSUE_FRAME(list[0], 0);
    asm volatile("cp.async.wait_group 1;" ::: "memory");   // Q arrived
    __syncthreads();

    // ---- bias[r][kl] = Qhf(row r, deswizzled) . Et[kl]
#pragma unroll
    for (int u = 0; u < 8; u++) {
        int id = tid + u * 128;
        int r = id >> 4, kl = id & 15;
        const float* erow = Et + kl * 68;
        float acc = 0.f;
#pragma unroll
        for (int ch = 0; ch < 8; ch++) {
            uint4 qv = *(const uint4*)(smem_raw + ATT_QHF + r * 128 + ((ch ^ (r & 7)) << 4));
            const __half2* hh = (const __half2*)&qv;
#pragma unroll
            for (int t = 0; t < 4; t++) {
                float2 f = __half22float2(hh[t]);
                acc += f.x * erow[ch * 8 + 2 * t] + f.y * erow[ch * 8 + 2 * t + 1];
            }
        }
        bias[r][kl] = acc;
    }

    // ---- Q A-fragments
    uint32_t qh[4][4];
    {
        int lrow = (lane & 7) + 8 * ((lane >> 3) & 1);
        int khalf = lane >> 4;
#pragma unroll
        for (int kt = 0; kt < 4; kt++) {
            int qr = r0 + lrow;
            int qc = kt * 2 + khalf;
            uint32_t off = qr * 128 + ((qc ^ (qr & 7)) << 4);
            ldsm4(qh[kt], sbase + ATT_QHF + off);
        }
    }
    __syncthreads();   // bias done; Et region (KV stage 1) now reusable

    int g4 = lane >> 2;
    float m0r = -INFINITY, m1r = -INFINITY, l0r = 0.f, l1r = 0.f;
    float O[8][4] = {};

    int klrow = (lane & 7) + 8 * (lane >> 4);
    int kchalf = (lane >> 3) & 1;
    int vlrow = (lane & 7) + 8 * ((lane >> 3) & 1);
    int vchalf = lane >> 4;

    for (int j = 0; j < nv; j++) {
        int stage = j & 1;
        if (j + 1 < nv) {
            ISSUE_FRAME(list[j + 1], (j + 1) & 1);
            asm volatile("cp.async.wait_group 1;" ::: "memory");
        } else {
            asm volatile("cp.async.wait_group 0;" ::: "memory");
        }
        __syncthreads();
        int kl = list[j];
        uint32_t khB = sbase + ATT_KV + stage * 16384;
        uint32_t vhB = khB + 8192;

        // ---- S = bias + Qhf.Khf
        float S[8][4];
        float bb0 = bias[r0 + g4][kl], bb1 = bias[r0 + 8 + g4][kl];
#pragma unroll
        for (int nt = 0; nt < 8; nt++) {
            S[nt][0] = bb0; S[nt][1] = bb0; S[nt][2] = bb1; S[nt][3] = bb1;
        }
#pragma unroll
        for (int kt = 0; kt < 4; kt++) {
#pragma unroll
            for (int np = 0; np < 4; np++) {
                int nr = np * 16 + klrow;
                int kc = kt * 2 + kchalf;
                uint32_t off = nr * 128 + ((kc ^ (nr & 7)) << 4);
                uint32_t kh[4];
                ldsm4(kh, khB + off);
                mma16816h(S[2 * np],     qh[kt], kh[0], kh[1]);
                mma16816h(S[2 * np + 1], qh[kt], kh[2], kh[3]);
            }
        }

        // ---- online softmax
        float mx0 = -INFINITY, mx1 = -INFINITY;
#pragma unroll
        for (int nt = 0; nt < 8; nt++) {
            mx0 = fmaxf(mx0, fmaxf(S[nt][0], S[nt][1]));
            mx1 = fmaxf(mx1, fmaxf(S[nt][2], S[nt][3]));
        }
        mx0 = fmaxf(mx0, __shfl_xor_sync(0xffffffffu, mx0, 1));
        mx0 = fmaxf(mx0, __shfl_xor_sync(0xffffffffu, mx0, 2));
        mx1 = fmaxf(mx1, __shfl_xor_sync(0xffffffffu, mx1, 1));
        mx1 = fmaxf(mx1, __shfl_xor_sync(0xffffffffu, mx1, 2));
        float mn0 = fmaxf(m0r, mx0), mn1 = fmaxf(m1r, mx1);
        float corr0 = __expf(m0r - mn0), corr1 = __expf(m1r - mn1);
        float sum0 = 0.f, sum1 = 0.f;
#pragma unroll
        for (int nt = 0; nt < 8; nt++) {
            S[nt][0] = __expf(S[nt][0] - mn0); S[nt][1] = __expf(S[nt][1] - mn0);
            S[nt][2] = __expf(S[nt][2] - mn1); S[nt][3] = __expf(S[nt][3] - mn1);
            sum0 += S[nt][0] + S[nt][1];
            sum1 += S[nt][2] + S[nt][3];
        }
        sum0 += __shfl_xor_sync(0xffffffffu, sum0, 1);
        sum0 += __shfl_xor_sync(0xffffffffu, sum0, 2);
        sum1 += __shfl_xor_sync(0xffffffffu, sum1, 1);
        sum1 += __shfl_xor_sync(0xffffffffu, sum1, 2);
        l0r = l0r * corr0 + sum0; m0r = mn0;
        l1r = l1r * corr1 + sum1; m1r = mn1;

        // ---- P fp16 A-fragments
        uint32_t ph[4][4];
#pragma unroll
        for (int kt = 0; kt < 4; kt++) {
#pragma unroll
            for (int q = 0; q < 4; q++) {
                int nt = 2 * kt + (q >> 1);
                ph[kt][q] = packh2(S[nt][(q & 1) * 2], S[nt][(q & 1) * 2 + 1]);
            }
        }

        // ---- O = O*corr + Phf.Vhf
#pragma unroll
        for (int nt = 0; nt < 8; nt++) {
            O[nt][0] *= corr0; O[nt][1] *= corr0; O[nt][2] *= corr1; O[nt][3] *= corr1;
        }
#pragma unroll
        for (int kt = 0; kt < 4; kt++) {
#pragma unroll
            for (int np = 0; np < 4; np++) {
                int vr = kt * 16 + vlrow;
                int vc = np * 2 + vchalf;
                uint32_t off = vr * 128 + ((vc ^ (vr & 7)) << 4);
                uint32_t vh[4];
                ldsm4t(vh, vhB + off);
                mma16816h(O[2 * np],     ph[kt], vh[0], vh[1]);
                mma16816h(O[2 * np + 1], ph[kt], vh[2], vh[3]);
            }
        }
        __syncthreads();
    }

    // ---- stage normalized O, coalesced store
    {
        float inv0 = 1.f / l0r, inv1 = 1.f / l1r;
        float* stage = (float*)smem_raw;   // [64][68] fp32 over dead KV
        int cl = 2 * (lane & 3);
#pragma unroll
        for (int nt = 0; nt < 8; nt++) {
            stage[(r0 + g4) * 68 + nt * 8 + cl]         = O[nt][0] * inv0;
            stage[(r0 + g4) * 68 + nt * 8 + cl + 1]     = O[nt][1] * inv0;
            stage[(r0 + 8 + g4) * 68 + nt * 8 + cl]     = O[nt][2] * inv1;
            stage[(r0 + 8 + g4) * 68 + nt * 8 + cl + 1] = O[nt][3] * inv1;
        }
        __syncthreads();
        for (int cc = tid; cc < 1024; cc += 128) {
            int row = cc >> 4, ch = cc & 15;
            float4 v = *(const float4*)(stage + row * 68 + ch * 4);
            *(float4*)(out + (size_t)((b * L_ + ql) * 64 + row) * D_ + h * HD_ + ch * 4) = v;
        }
    }
}

// ---------------------------------------------------------------------------
extern "C" void kernel_launch(void* const* d_in, const int* in_sizes, int n_in,
                              void* d_out, int out_size) {
    const float* x    = (const float*)d_in[0];
    const float* te   = (const float*)d_in[1];
    const int*   pos  = (const int*)d_in[2];
    const int*   mask = (const int*)d_in[3];
    const float* Wqkv = (const float*)d_in[4];
    const float* Wt   = (const float*)d_in[5];
    const float* emb  = (const float*)d_in[6];
    float* out = (float*)d_out;

    cudaFuncSetAttribute(qkv_gemm, cudaFuncAttributeMaxDynamicSharedMemorySize, GEMM_SMEM);
    cudaFuncSetAttribute(attn_kernel, cudaFuncAttributeMaxDynamicSharedMemorySize, ATT_SMEM);

    split_kernel<<<(XQUADS + WQUADS) / 256, 256>>>(x, Wqkv);
    qkv_gemm<<<dim3(E3_ / 128, 4096 / 128), 256, GEMM_SMEM>>>(te, Wt);
    attn_kernel<<<dim3(L_, H_, B_), 128, ATT_SMEM>>>(pos, mask, emb, out);
}